// round 17
// baseline (speedup 1.0000x reference)
#include <cuda_runtime.h>

#define HID 4096
#define GATES (3*HID)
#define NVOCAB 256
#define ROWS_PER_BLOCK 8     // 8 warps, warp-per-row
#define SEG_BLOCKS (GATES / ROWS_PER_BLOCK)  // 1536 blocks per matrix
#define MV1_GBLKS 8          // K2: blocks 0-7 compute gate0 slices
#define HH1_BASE  MV1_GBLKS                          // 8..1543: W_hh1 streamers
#define IH1_BASE  (MV1_GBLKS + SEG_BLOCKS)           // 1544..3079: W_ih1 workers
#define G1_BASE   (MV1_GBLKS + 2 * SEG_BLOCKS)       // 3080..3087: gate1 slices
#define DECW_BASE (G1_BASE + 8)                      // 3088..3119: dec workers
#define K2_GRID   (DECW_BASE + 32)                   // 3120
#define STREAMERS (2 * SEG_BLOCKS)                   // 3072 bump g_wdone

// Scratch (allocation-free rule: __device__ globals). 16B-aligned for float4.
__device__ __align__(16) float g_gi0[GATES];
__device__ __align__(16) float g_gh0[GATES];
__device__ __align__(16) float g_gh1[GATES];
__device__ __align__(16) float g_gi1[GATES];
__device__ __align__(16) float g_h0[HID];
__device__ __align__(16) float g_h1[HID];
// Replay-safe monotonic counters (never reset; epochs via division).
__device__ unsigned long long g_done0;   // +8 per replay    (gate0 blocks)
__device__ unsigned long long g_warr0;   // +1536 per replay (W_ih1 tickets)
__device__ unsigned long long g_wdone;   // +3072 per replay (hh1+ih1 blocks)
__device__ unsigned long long g_garr1;   // +8 per replay    (gate1 tickets)
__device__ unsigned long long g_done1;   // +8 per replay    (gate1 done)
__device__ unsigned long long g_warr1;   // +32 per replay   (dec tickets)

__device__ __forceinline__ float sigmoidf_(float v) {
    return __fdividef(1.0f, 1.0f + __expf(-v));
}
__device__ __forceinline__ float tanhf_(float v) {
    return __fdividef(2.0f, 1.0f + __expf(-2.0f * v)) - 1.0f;
}

// Prefetch this warp's 16KB weight row into L2 (4 x 128B lines per lane).
__device__ __forceinline__ void prefetch_row_l2(const float* wrow, int lane) {
    const char* p = (const char*)wrow;
    #pragma unroll
    for (int k = 0; k < 4; k++)
        asm volatile("prefetch.global.L2 [%0];" :: "l"(p + (lane * 4 + k) * 128));
}

// Warp dot over HID=4096; float4 + __ldcs (evict-first) — the proven engine.
__device__ __forceinline__ float warp_dot_row(const float4* __restrict__ w4,
                                              const float4* __restrict__ sx4,
                                              int lane) {
    float acc = 0.0f;
    #pragma unroll
    for (int i = 0; i < HID / 4 / 32; i++) {       // 32 iterations
        float4 a  = __ldcs(w4 + lane + 32 * i);
        float4 xv = sx4[lane + 32 * i];
        acc += a.x * xv.x + a.y * xv.y + a.z * xv.z + a.w * xv.w;
    }
    #pragma unroll
    for (int off = 16; off; off >>= 1)
        acc += __shfl_down_sync(0xffffffffu, acc, off);
    return acc;
}

// GRU gate pass for one float4 item.
__device__ __forceinline__ float4 gate_item4(
    const float4* gi, const float4* gh, const float4* hp4, int j4)
{
    float4 ir = gi[j4];
    float4 hr = gh[j4];
    float4 iz = gi[j4 + HID/4];
    float4 hz = gh[j4 + HID/4];
    float4 in_ = gi[j4 + 2*(HID/4)];
    float4 hn  = gh[j4 + 2*(HID/4)];
    float4 hp = hp4[j4];
    float4 h;
    {
        float r = sigmoidf_(ir.x + hr.x), z = sigmoidf_(iz.x + hz.x);
        float n = tanhf_(in_.x + r * hn.x); h.x = (1.0f - z) * n + z * hp.x;
    }
    {
        float r = sigmoidf_(ir.y + hr.y), z = sigmoidf_(iz.y + hz.y);
        float n = tanhf_(in_.y + r * hn.y); h.y = (1.0f - z) * n + z * hp.y;
    }
    {
        float r = sigmoidf_(ir.z + hr.z), z = sigmoidf_(iz.z + hz.z);
        float n = tanhf_(in_.z + r * hn.z); h.z = (1.0f - z) * n + z * hp.z;
    }
    {
        float r = sigmoidf_(ir.w + hr.w), z = sigmoidf_(iz.w + hz.w);
        float n = tanhf_(in_.w + r * hn.w); h.w = (1.0f - z) * n + z * hp.w;
    }
    return h;
}

// Publish this block's global writes and bump a done counter. (R14-proven.)
__device__ __forceinline__ void publish_done(unsigned long long* ctr) {
    __syncthreads();
    __threadfence();
    if (threadIdx.x == 0) atomicAdd(ctr, 1ULL);
}

// Spin until ctr >= target (thread 0), then block-wide acquire.
__device__ __forceinline__ void wait_count(unsigned long long* ctr,
                                           unsigned long long target) {
    if (threadIdx.x == 0) {
        while (*((volatile unsigned long long*)ctr) < target) __nanosleep(32);
    }
    __syncthreads();
    __threadfence();
}

// ---------------------------------------------------------------------------
// K1: gi0 = W_ih0 @ emb[inp] ; gh0 = W_hh0 @ h0 (+biases). 402 MB, 3072 blks.
// ---------------------------------------------------------------------------
__global__ __launch_bounds__(256, 6) void mv3_kernel(
    const int* __restrict__ inp, const float* __restrict__ hidden,
    const float* __restrict__ emb,
    const float* __restrict__ Wih0, const float* __restrict__ Whh0,
    const float* __restrict__ bih0, const float* __restrict__ bhh0)
{
    __shared__ __align__(16) float sx[HID];
    const int warp = threadIdx.x >> 5;
    const int lane = threadIdx.x & 31;

    const int seg    = blockIdx.x / SEG_BLOCKS;      // 0,1
    const int segblk = blockIdx.x % SEG_BLOCKS;

    const float* W; const float* b; const float* x; float* y;
    if (seg == 0) { W = Wih0; b = bih0; x = emb + (size_t)inp[0] * HID; y = g_gi0; }
    else          { W = Whh0; b = bhh0; x = hidden;                     y = g_gh0; }

    for (int i = threadIdx.x; i < HID / 4; i += 256)
        ((float4*)sx)[i] = ((const float4*)x)[i];
    __syncthreads();

    const int row = segblk * ROWS_PER_BLOCK + warp;
    float acc = warp_dot_row((const float4*)(W + (size_t)row * HID),
                             (const float4*)sx, lane);
    if (lane == 0) y[row] = acc + b[row];
    cudaTriggerProgrammaticLaunchCompletion();
}

// ---------------------------------------------------------------------------
// K2: five roles, grid = 3120:
//   0..7       gate0 slices: PDL-sync mv3, compute h0_new, bump g_done0.
//   8..1543    W_hh1 streamers: inputs only, no sync — gh1 rows; bump g_wdone.
//   1544..3079 W_ih1 workers: prefetch, PDL-sync, wait g_done0, gi1 rows;
//              bump g_wdone.
//   3080..3087 gate1 slices: wait g_wdone (gi1+gh1 complete), h1_new slices;
//              bump g_done1.
//   3088..3119 dec workers: prefetch W_dec row, wait g_done1, decoder matvec.
// All counters monotonic (replay-safe); spinners are only the last 40 blocks.
// ---------------------------------------------------------------------------
__global__ __launch_bounds__(256, 6) void mv1_kernel(
    const float* __restrict__ Wih1, const float* __restrict__ Whh1,
    const float* __restrict__ bih1, const float* __restrict__ bhh1,
    const float* __restrict__ Wdec, const float* __restrict__ bdec,
    const float* __restrict__ hidden, float* __restrict__ out)
{
    __shared__ __align__(16) float sx[HID];
    const int warp = threadIdx.x >> 5;
    const int lane = threadIdx.x & 31;

    if (blockIdx.x < MV1_GBLKS) {
        // ---- gate0 slice block ----
        cudaGridDependencySynchronize();      // mv3 done: gi0/gh0 ready
        const int slice = blockIdx.x;         // 0..7
        if (threadIdx.x < 128) {
            const int j4 = slice * 128 + threadIdx.x;    // 128 float4 items
            float4 h = gate_item4((const float4*)g_gi0, (const float4*)g_gh0,
                                  (const float4*)hidden, j4);
            ((float4*)g_h0)[j4] = h;
            ((float4*)(out + NVOCAB))[j4] = h;           // new_h[0]
        }
        publish_done(&g_done0);
        return;
    }

    if (blockIdx.x < IH1_BASE) {
        // ---- W_hh1 streamer: inputs only, stream immediately ----
        const int row = (blockIdx.x - HH1_BASE) * ROWS_PER_BLOCK + warp;
        for (int i = threadIdx.x; i < HID / 4; i += 256)
            ((float4*)sx)[i] = ((const float4*)(hidden + HID))[i];
        __syncthreads();
        float acc = warp_dot_row((const float4*)(Whh1 + (size_t)row * HID),
                                 (const float4*)sx, lane);
        if (lane == 0) g_gh1[row] = acc + bhh1[row];
        publish_done(&g_wdone);
        return;
    }

    if (blockIdx.x < G1_BASE) {
        // ---- W_ih1 worker ----
        const int row = (blockIdx.x - IH1_BASE) * ROWS_PER_BLOCK + warp;
        const float* wrow = Wih1 + (size_t)row * HID;

        prefetch_row_l2(wrow, lane);      // independent of producer output
        cudaGridDependencySynchronize();

        __shared__ unsigned long long s_t;
        if (threadIdx.x == 0) s_t = atomicAdd(&g_warr0, 1ULL);
        __syncthreads();
        const unsigned long long epoch = s_t / (unsigned long long)SEG_BLOCKS;
        wait_count(&g_done0, (epoch + 1ULL) * (unsigned long long)MV1_GBLKS);

        for (int i = threadIdx.x; i < HID / 4; i += 256)
            ((float4*)sx)[i] = ((const float4*)g_h0)[i];
        __syncthreads();

        float acc = warp_dot_row((const float4*)wrow, (const float4*)sx, lane);
        if (lane == 0) g_gi1[row] = acc + bih1[row];
        publish_done(&g_wdone);
        return;
    }

    if (blockIdx.x < DECW_BASE) {
        // ---- gate1 slice block (all deps in-kernel: gi1 + gh1) ----
        __shared__ unsigned long long s_t;
        if (threadIdx.x == 0) s_t = atomicAdd(&g_garr1, 1ULL);
        __syncthreads();
        const unsigned long long epoch = s_t / 8ULL;
        wait_count(&g_wdone, (epoch + 1ULL) * (unsigned long long)STREAMERS);

        const int slice = blockIdx.x - G1_BASE;          // 0..7
        if (threadIdx.x < 128) {
            const int j4 = slice * 128 + threadIdx.x;
            float4 h = gate_item4((const float4*)g_gi1, (const float4*)g_gh1,
                                  (const float4*)(hidden + HID), j4);
            ((float4*)g_h1)[j4] = h;
            ((float4*)(out + NVOCAB + HID))[j4] = h;     // new_h[1]
        }
        publish_done(&g_done1);
        return;
    }

    // ---- dec worker (all deps in-kernel: g_h1) ----
    {
        const int row = (blockIdx.x - DECW_BASE) * ROWS_PER_BLOCK + warp; // 0..255
        const float* wrow = Wdec + (size_t)row * HID;

        prefetch_row_l2(wrow, lane);      // overlaps the W_ih1 stream

        __shared__ unsigned long long s_t;
        if (threadIdx.x == 0) s_t = atomicAdd(&g_warr1, 1ULL);
        __syncthreads();
        const unsigned long long epoch = s_t / 32ULL;
        wait_count(&g_done1, (epoch + 1ULL) * 8ULL);

        for (int i = threadIdx.x; i < HID / 4; i += 256)
            ((float4*)sx)[i] = ((const float4*)g_h1)[i];
        __syncthreads();

        float acc = warp_dot_row((const float4*)wrow, (const float4*)sx, lane);
        if (lane == 0) out[row] = acc + bdec[row];
    }
}

// ---------------------------------------------------------------------------
// Inputs (metadata order):
// 0 inp(int32,1) 1 hidden(2*4096) 2 emb(256*4096)
// 3 W_ih0 4 W_hh0 5 b_ih0 6 b_hh0
// 7 W_ih1 8 W_hh1 9 b_ih1 10 b_hh1
// 11 W_dec 12 b_dec
// Output: [logits(256) | h0_new(4096) | h1_new(4096)]
// ---------------------------------------------------------------------------
template <typename... Args>
static inline void launch_pdl(void (*kern)(Args...), dim3 grid, dim3 block,
                              Args... args)
{
    cudaLaunchConfig_t cfg = {};
    cfg.gridDim = grid;
    cfg.blockDim = block;
    cfg.dynamicSmemBytes = 0;
    cfg.stream = 0;
    cudaLaunchAttribute attr[1];
    attr[0].id = cudaLaunchAttributeProgrammaticStreamSerialization;
    attr[0].val.programmaticStreamSerializationAllowed = 1;
    cfg.attrs = attr;
    cfg.numAttrs = 1;
    cudaLaunchKernelEx(&cfg, kern, args...);
}

extern "C" void kernel_launch(void* const* d_in, const int* in_sizes, int n_in,
                              void* d_out, int out_size)
{
    const int*   inp    = (const int*)  d_in[0];
    const float* hidden = (const float*)d_in[1];
    const float* emb    = (const float*)d_in[2];
    const float* Wih0   = (const float*)d_in[3];
    const float* Whh0   = (const float*)d_in[4];
    const float* bih0   = (const float*)d_in[5];
    const float* bhh0   = (const float*)d_in[6];
    const float* Wih1   = (const float*)d_in[7];
    const float* Whh1   = (const float*)d_in[8];
    const float* bih1   = (const float*)d_in[9];
    const float* bhh1   = (const float*)d_in[10];
    const float* Wdec   = (const float*)d_in[11];
    const float* bdec   = (const float*)d_in[12];
    float* out = (float*)d_out;

    mv3_kernel<<<2 * SEG_BLOCKS, 256>>>(inp, hidden, emb, Wih0, Whh0,
                                        bih0, bhh0);
    launch_pdl(mv1_kernel, dim3(K2_GRID), dim3(256),
               Wih1, Whh1, bih1, bhh1, Wdec, bdec, hidden, out);
}